// round 10
// baseline (speedup 1.0000x reference)
#include <cuda_runtime.h>
#include <math.h>

#define BS   64
#define CIN  256
#define II   1024
#define J    10
#define D    32
#define OD   320
#define NTILE 4
#define TILE_I 256   // II / NTILE

typedef unsigned long long ull;

// ---------------- scratch (static device globals; zero-init, no allocation) ----
__device__ float g_xsump[BS*NTILE*CIN];
__device__ float g_u    [BS*J*CIN];
__device__ float g_vb   [BS*J];
__device__ float g_ypart[BS*NTILE*J*CIN];
__device__ float g_cpart[BS*NTILE*J];
__device__ unsigned int g_ctr [3*BS];   // software barrier counters
__device__ unsigned int g_flag[2*BS];   // sv-done flags

// ---------------- f32x2 helpers ----------------
static __device__ __forceinline__ void ffma2(ull &d, ull a, ull b) {
    asm("fma.rn.f32x2 %0, %1, %2, %0;" : "+l"(d) : "l"(a), "l"(b));
}
static __device__ __forceinline__ ull add2(ull a, ull b) {
    ull r; asm("add.rn.f32x2 %0, %1, %2;" : "=l"(r) : "l"(a), "l"(b)); return r;
}
static __device__ __forceinline__ ull dup2(float x) {
    unsigned int u = __float_as_uint(x);
    return ((ull)u << 32) | (ull)u;
}
static __device__ __forceinline__ float lo2(ull v) {
    return __uint_as_float((unsigned int)(v & 0xffffffffu));
}
static __device__ __forceinline__ float hi2(ull v) {
    return __uint_as_float((unsigned int)(v >> 32));
}

// ---------------- inter-block sync (threadFenceReduction pattern) -------------
static __device__ __forceinline__ void bar_arrive(unsigned int* c) {
    __syncthreads();
    __threadfence();
    if (threadIdx.x == 0) atomicAdd(c, 1u);
}
static __device__ __forceinline__ void bar_wait_full(unsigned int* c) {
    if (threadIdx.x == 0)
        while (atomicAdd(c, 0u) < NTILE) __nanosleep(64);
    __syncthreads();
    __threadfence();
}
static __device__ __forceinline__ void flag_set(unsigned int* f) {
    __syncthreads();
    __threadfence();
    if (threadIdx.x == 0) atomicExch(f, 1u);
}
static __device__ __forceinline__ void flag_wait(unsigned int* f) {
    if (threadIdx.x == 0)
        while (atomicAdd(f, 0u) == 0u) __nanosleep(64);
    __syncthreads();
    __threadfence();
}

// ---------------- elected-block sv: ysm -> s -> squash(v) -> (u,vb) | out -----
// ysm: [j*CIN+c] rows if use_yj else single row [c]. csum in smem.
static __device__ __forceinline__ void sv_compute(
    const float* __restrict__ W, const float* __restrict__ Wb,
    float* __restrict__ out, const float* ysm, const float* csum,
    float* ssm, float* vsm, float* coef,
    int b, int use_yj, int accum, int final_out)
{
    int t = threadIdx.x, w = t >> 5, l = t & 31;

    // s[o] = W[o,:] . y_row(j) + csum[j]*Wb[o]; warp-collective dots
    for (int o = w; o < OD; o += 8) {
        int jj = o >> 5;
        const float4* wr = (const float4*)(W + (size_t)o * CIN);
        const float4* y4 = (const float4*)(ysm + (use_yj ? jj * CIN : 0));
        float4 w0 = wr[l], w1 = wr[l + 32];
        float4 ya = y4[l], yb = y4[l + 32];
        float a = w0.x*ya.x + w0.y*ya.y + w0.z*ya.z + w0.w*ya.w
                + w1.x*yb.x + w1.y*yb.y + w1.z*yb.z + w1.w*yb.w;
        #pragma unroll
        for (int o2 = 16; o2; o2 >>= 1) a += __shfl_xor_sync(0xffffffffu, a, o2);
        if (l == 0) ssm[o] = a + csum[jj] * Wb[o];
    }
    __syncthreads();

    if (t < J) {
        float ns = 0.0f;
        #pragma unroll
        for (int d = 0; d < D; d++) { float s = ssm[t * D + d]; ns += s * s; }
        coef[t] = ns / ((1.0f + ns) * sqrtf(ns));
    }
    __syncthreads();

    #pragma unroll
    for (int o = t; o < OD; o += 256) {
        float v = ssm[o] * coef[o >> 5];
        vsm[o] = v;
        if (final_out) out[b * OD + o] = v;
    }
    __syncthreads();

    if (!final_out) {
        // u[j][c=t] = sum_d v[j,d]*W[jD+d,c]  (W coalesced, vsm broadcast)
        #pragma unroll
        for (int j = 0; j < J; j++) {
            float a = 0.0f;
            #pragma unroll
            for (int d = 0; d < D; d++)
                a = fmaf(vsm[j * D + d], W[(size_t)(j * D + d) * CIN + t], a);
            size_t gi = ((size_t)b * J + j) * CIN + t;
            g_u[gi] = accum ? g_u[gi] + a : a;
        }
        if (t < J) {
            float a = 0.0f;
            #pragma unroll
            for (int d = 0; d < D; d++) a += vsm[t * D + d] * Wb[t * D + d];
            int gi = b * J + t;
            g_vb[gi] = accum ? g_vb[gi] + a : a;
        }
    }
}

// ---------------- per-tile routing pass (logits->softmax->ypart,cpart) -------
static __device__ __forceinline__ void do_pass(
    const float* __restrict__ xb, int i0, int b, int tile,
    ull* uperm, float* xsm, float* cssm, float* vbs)
{
    int t = threadIdx.x, w = t >> 5, l = t & 31;

    const float* gu = g_u + (size_t)b * J * CIN;
    #pragma unroll
    for (int k = 0; k < J; k++)
        uperm[k * 256 + (t & 63) * 4 + (t >> 6)] = dup2(gu[k * 256 + t]);
    if (t < J) vbs[t] = g_vb[b * J + t];
    __syncthreads();

    // phase A: logits, 4 i's per thread via LDG.128 columns, 4-way c-split
    int cg = l >> 3, qi = l & 7;
    int ib = w * 32 + qi * 4;
    ull a0[J], a1[J];
    #pragma unroll
    for (int j = 0; j < J; j++) { a0[j] = 0ull; a1[j] = 0ull; }
    {
        const float* xp = xb + (size_t)cg * 64 * II + i0 + ib;
        #pragma unroll 4
        for (int cc = 0; cc < 64; cc++) {
            ulonglong2 xv = *(const ulonglong2*)(xp + (size_t)cc * II);
            const ull* up = uperm + cc * 4 + cg;
            #pragma unroll
            for (int j = 0; j < J; j++) {
                ull ud = up[j * 256];
                ffma2(a0[j], ud, xv.x);
                ffma2(a1[j], ud, xv.y);
            }
        }
    }
    #pragma unroll
    for (int j = 0; j < J; j++) {
        a0[j] = add2(a0[j], __shfl_xor_sync(0xffffffffu, a0[j], 8));
        a1[j] = add2(a1[j], __shfl_xor_sync(0xffffffffu, a1[j], 8));
        a0[j] = add2(a0[j], __shfl_xor_sync(0xffffffffu, a0[j], 16));
        a1[j] = add2(a1[j], __shfl_xor_sync(0xffffffffu, a1[j], 16));
    }
    if (cg == 0) {
        float lg[J][4];
        #pragma unroll
        for (int j = 0; j < J; j++) {
            lg[j][0] = lo2(a0[j]) + vbs[j];
            lg[j][1] = hi2(a0[j]) + vbs[j];
            lg[j][2] = lo2(a1[j]) + vbs[j];
            lg[j][3] = hi2(a1[j]) + vbs[j];
        }
        float r[4];
        #pragma unroll
        for (int i = 0; i < 4; i++) {
            float m = lg[0][i];
            #pragma unroll
            for (int j = 1; j < J; j++) m = fmaxf(m, lg[j][i]);
            float s = 0.0f;
            #pragma unroll
            for (int j = 0; j < J; j++) { lg[j][i] = __expf(lg[j][i] - m); s += lg[j][i]; }
            r[i] = 1.0f / s;
        }
        #pragma unroll
        for (int j = 0; j < J; j++)
            *(float4*)(cssm + j * TILE_I + ib) =
                make_float4(lg[j][0]*r[0], lg[j][1]*r[1], lg[j][2]*r[2], lg[j][3]*r[3]);
    }
    __syncthreads();

    // csum partials
    for (int j = w; j < J; j += 8) {
        const float4* p4 = (const float4*)(cssm + j * TILE_I);
        float4 A = p4[l * 2], B4 = p4[l * 2 + 1];
        float sc = A.x + A.y + A.z + A.w + B4.x + B4.y + B4.z + B4.w;
        #pragma unroll
        for (int o = 16; o; o >>= 1) sc += __shfl_xor_sync(0xffffffffu, sc, o);
        if (l == 0) g_cpart[(b * NTILE + tile) * J + j] = sc;
    }

    // phase B: ypart[j][c=t] over 16-i staged chunks (xsm aliases uperm)
    ull y0[J], y1[J];
    #pragma unroll
    for (int j = 0; j < J; j++) { y0[j] = 0ull; y1[j] = 0ull; }
    int srow = t >> 2, sq = t & 3;
    #pragma unroll 1
    for (int ch = 0; ch < TILE_I / 16; ch++) {
        __syncthreads();
        #pragma unroll
        for (int s = 0; s < 4; s++) {
            int row = s * 64 + srow;
            float4 v = *(const float4*)(xb + (size_t)row * II + i0 + ch * 16 + sq * 4);
            *(float4*)(xsm + row * 20 + sq * 4) = v;
        }
        __syncthreads();
        #pragma unroll
        for (int g = 0; g < 4; g++) {
            ulonglong2 xv = *(const ulonglong2*)(xsm + t * 20 + g * 4);
            int ii = ch * 16 + g * 4;
            #pragma unroll
            for (int j = 0; j < J; j++) {
                ulonglong2 cv = *(const ulonglong2*)(cssm + j * TILE_I + ii);
                ffma2(y0[j], cv.x, xv.x);
                ffma2(y1[j], cv.y, xv.y);
            }
        }
    }
    __syncthreads();   // all cssm/xsm reads done before any later reuse
    #pragma unroll
    for (int j = 0; j < J; j++)
        g_ypart[(((size_t)b * NTILE + tile) * J + j) * CIN + t] =
            (lo2(y0[j]) + hi2(y0[j])) + (lo2(y1[j]) + hi2(y1[j]));
}

// ---------------- the single fused kernel ----------------
__global__ void __launch_bounds__(256, 2) k_main(
    const float* __restrict__ x, const float* __restrict__ W,
    const float* __restrict__ Wb, float* __restrict__ out)
{
    __shared__ __align__(16) char  sm1[20480];      // uperm (A) / xsm (B, stage0)
    __shared__ __align__(16) float sm2[J * TILE_I]; // cssm / ysm (2560 floats)
    __shared__ __align__(16) float ssm[OD];
    __shared__ __align__(16) float vsm[OD];
    __shared__ float coef[J];
    __shared__ float csum[J];
    __shared__ float vbs[J];

    ull*   uperm = (ull*)sm1;
    float* xsm   = (float*)sm1;
    float* cssm  = sm2;
    float* ysm   = sm2;

    int tile = blockIdx.x, b = blockIdx.y, t = threadIdx.x;
    const float* xb = x + (size_t)b * CIN * II;
    int i0 = tile * TILE_I;
    int srow = t >> 2, sq = t & 3;
    bool elected = (tile == 0);

    // ---- stage 0: xsum partial over this tile (staged chunks, thread=c) ----
    {
        float xs = 0.0f;
        #pragma unroll 1
        for (int ch = 0; ch < TILE_I / 16; ch++) {
            __syncthreads();
            #pragma unroll
            for (int s = 0; s < 4; s++) {
                int row = s * 64 + srow;
                float4 v = *(const float4*)(xb + (size_t)row * II + i0 + ch * 16 + sq * 4);
                *(float4*)(xsm + row * 20 + sq * 4) = v;
            }
            __syncthreads();
            #pragma unroll
            for (int g = 0; g < 4; g++) {
                float4 v = *(const float4*)(xsm + t * 20 + g * 4);
                xs += (v.x + v.y) + (v.z + v.w);
            }
        }
        g_xsump[(b * NTILE + tile) * CIN + t] = xs;
    }
    bar_arrive(&g_ctr[b]);

    // ---- sv1 (elected): y1 = sum(xsump)/J, uniform over j ----
    if (elected) {
        bar_wait_full(&g_ctr[b]);
        const float* xp = g_xsump + (size_t)b * NTILE * CIN + t;
        ysm[t] = (xp[0] + xp[CIN] + xp[2 * CIN] + xp[3 * CIN]) * (1.0f / (float)J);
        if (t < J) csum[t] = (float)II / (float)J;
        __syncthreads();
        sv_compute(W, Wb, out, ysm, csum, ssm, vsm, coef, b, 0, 0, 0);
        flag_set(&g_flag[b]);
    }
    flag_wait(&g_flag[b]);

    // ---- iter2 pass ----
    do_pass(xb, i0, b, tile, uperm, xsm, cssm, vbs);
    bar_arrive(&g_ctr[BS + b]);

    // ---- sv2 (elected) ----
    if (elected) {
        bar_wait_full(&g_ctr[BS + b]);
        #pragma unroll
        for (int j = 0; j < J; j++) {
            const float* yp = g_ypart + (((size_t)b * NTILE) * J + j) * CIN + t;
            ysm[j * CIN + t] = (yp[0] + yp[(size_t)J * CIN])
                             + (yp[2 * (size_t)J * CIN] + yp[3 * (size_t)J * CIN]);
        }
        if (t < J) {
            const float* cp = g_cpart + (b * NTILE) * J + t;
            csum[t] = (cp[0] + cp[J]) + (cp[2 * J] + cp[3 * J]);
        }
        __syncthreads();
        sv_compute(W, Wb, out, ysm, csum, ssm, vsm, coef, b, 1, 1, 0);
        flag_set(&g_flag[BS + b]);
    }
    flag_wait(&g_flag[BS + b]);

    // ---- iter3 pass ----
    do_pass(xb, i0, b, tile, uperm, xsm, cssm, vbs);
    bar_arrive(&g_ctr[2 * BS + b]);

    // ---- sv3 (elected): final v -> out, then reset sync state ----
    if (elected) {
        bar_wait_full(&g_ctr[2 * BS + b]);
        #pragma unroll
        for (int j = 0; j < J; j++) {
            const float* yp = g_ypart + (((size_t)b * NTILE) * J + j) * CIN + t;
            ysm[j * CIN + t] = (yp[0] + yp[(size_t)J * CIN])
                             + (yp[2 * (size_t)J * CIN] + yp[3 * (size_t)J * CIN]);
        }
        if (t < J) {
            const float* cp = g_cpart + (b * NTILE) * J + t;
            csum[t] = (cp[0] + cp[J]) + (cp[2 * J] + cp[3 * J]);
        }
        __syncthreads();
        sv_compute(W, Wb, out, ysm, csum, ssm, vsm, coef, b, 1, 0, 1);
        __syncthreads();
        if (t == 0) {   // reset for next graph replay (all peers already exited waits)
            g_ctr[b] = 0; g_ctr[BS + b] = 0; g_ctr[2 * BS + b] = 0;
            g_flag[b] = 0; g_flag[BS + b] = 0;
        }
    }
}

// ---------------- launch ----------------
extern "C" void kernel_launch(void* const* d_in, const int* in_sizes, int n_in,
                              void* d_out, int out_size) {
    const float* x  = (const float*)d_in[0];   // [64,256,32,32]
    const float* W  = (const float*)d_in[1];   // [320,256]
    const float* Wb = (const float*)d_in[2];   // [320]
    float* out = (float*)d_out;                // [64,10,32]

    k_main<<<dim3(NTILE, BS), 256>>>(x, W, Wb, out);
}

// round 12
// speedup vs baseline: 1.4207x; 1.4207x over previous
#include <cuda_runtime.h>
#include <math.h>

#define BS   64
#define CIN  256
#define II   1024
#define J    10
#define D    32
#define NP   16      // tiles per batch
#define TI   64      // II / NP

typedef unsigned long long ull;

// ---------------- scratch (static device globals; no allocation) ----------------
__device__ float g_xsum [BS*CIN];
__device__ float g_u    [BS*J*CIN];          // accumulated u_j = W_j^T v_j
__device__ float g_vb   [BS*J];
__device__ float g_ypart[BS*NP*J*CIN];
__device__ float g_cpart[BS*NP*J];

// smem layout (dynamic, bytes)
#define SM_XT    0        // float xt[256*66]                 67584
#define SM_USM   67584    // ull usm[10*256] / psm[8*32*10]   20480
#define SM_CSSM  88064    // float cssm[10*64]                 2560
#define SM_VBS   90624    // float vbs[10]
#define SM_CSW   90688    // float csw[2*10]
#define SM_TOT   90880

// ---------------- f32x2 helpers ----------------
static __device__ __forceinline__ void ffma2(ull &d, ull a, ull b) {
    asm("fma.rn.f32x2 %0, %1, %2, %0;" : "+l"(d) : "l"(a), "l"(b));
}
static __device__ __forceinline__ ull dup2(float x) {
    unsigned int u = __float_as_uint(x);
    return ((ull)u << 32) | (ull)u;
}
static __device__ __forceinline__ float lo2(ull v) {
    return __uint_as_float((unsigned int)(v & 0xffffffffu));
}
static __device__ __forceinline__ float hi2(ull v) {
    return __uint_as_float((unsigned int)(v >> 32));
}

// ---------------- K1: xsum[b,c] = sum_i x[b,c,i] ----------------
__global__ void k_xsum(const float* __restrict__ x) {
    int warp = (blockIdx.x * blockDim.x + threadIdx.x) >> 5;   // row = b*CIN + c
    int lane = threadIdx.x & 31;
    if (warp >= BS * CIN) return;
    const float4* row = (const float4*)(x + (size_t)warp * II);
    float s = 0.0f;
    #pragma unroll
    for (int k = 0; k < II / 128; k++) {
        float4 v = row[k * 32 + lane];
        s += v.x + v.y + v.z + v.w;
    }
    #pragma unroll
    for (int off = 16; off; off >>= 1) s += __shfl_xor_sync(0xffffffffu, s, off);
    if (lane == 0) g_xsum[warp] = s;
}

// ---------------- K_sv (R2-proven): per (b,j) block -------------------------
// grid (J, BS), 256 threads. mode: 0 iter1, 1 middle, 2 final
__global__ void __launch_bounds__(256) k_sv(const float* __restrict__ W,
                                            const float* __restrict__ Wb,
                                            float* __restrict__ out, int mode) {
    int j = blockIdx.x, b = blockIdx.y, t = threadIdx.x;
    int wid = t >> 5, lane = t & 31;
    __shared__ __align__(16) float ysm[CIN];
    __shared__ float ssm[D];
    __shared__ float vsm[D];
    __shared__ float csum_s;

    float yv;
    if (mode == 0) {
        yv = g_xsum[b * CIN + t] * (1.0f / (float)J);
        if (t == 0) csum_s = (float)II / (float)J;
    } else {
        yv = 0.0f;
        #pragma unroll
        for (int p = 0; p < NP; p++)
            yv += g_ypart[(((size_t)b * NP + p) * J + j) * CIN + t];
        if (t == 0) {
            float a = 0.0f;
            #pragma unroll
            for (int p = 0; p < NP; p++) a += g_cpart[(b * NP + p) * J + j];
            csum_s = a;
        }
    }
    ysm[t] = yv;
    __syncthreads();
    float csum = csum_s;

    // s[d] = W[jD+d,:] . y + csum*Wb[jD+d]; warp w handles d = w, w+8, ...
    for (int d = wid; d < D; d += 8) {
        const float4* wr = (const float4*)(W + (size_t)(j * D + d) * CIN);
        const float4* yr = (const float4*)ysm;
        float4 w0 = wr[lane * 2], w1 = wr[lane * 2 + 1];
        float4 y0 = yr[lane * 2], y1 = yr[lane * 2 + 1];
        float a = w0.x * y0.x + w0.y * y0.y + w0.z * y0.z + w0.w * y0.w
                + w1.x * y1.x + w1.y * y1.y + w1.z * y1.z + w1.w * y1.w;
        #pragma unroll
        for (int off = 16; off; off >>= 1) a += __shfl_xor_sync(0xffffffffu, a, off);
        if (lane == 0) ssm[d] = a + csum * Wb[j * D + d];
    }
    __syncthreads();

    if (wid == 0) {
        float s = ssm[lane];
        float ns = s * s;
        #pragma unroll
        for (int off = 16; off; off >>= 1) ns += __shfl_xor_sync(0xffffffffu, ns, off);
        float coef = ns / ((1.0f + ns) * sqrtf(ns));
        float v = s * coef;
        vsm[lane] = v;
        if (mode == 2) {
            out[(b * J + j) * D + lane] = v;
        } else {
            float pv = v * Wb[j * D + lane];
            #pragma unroll
            for (int off = 16; off; off >>= 1) pv += __shfl_xor_sync(0xffffffffu, pv, off);
            if (lane == 0) g_vb[b * J + j] = (mode == 0) ? pv : g_vb[b * J + j] + pv;
        }
    }
    __syncthreads();

    if (mode != 2) {
        float a = 0.0f;
        #pragma unroll
        for (int d = 0; d < D; d++)
            a = fmaf(vsm[d], W[(size_t)(j * D + d) * CIN + t], a);
        size_t idx = ((size_t)b * J + j) * CIN + t;
        g_u[idx] = (mode == 0) ? a : g_u[idx] + a;
    }
}

// ---------------- K_fused: one routing pass, x read ONCE per tile ------------
// grid (NP, BS), 256 threads, dynamic smem SM_TOT.
// Phase A: warp w owns c in [32w, 32w+32); lane ip owns i-pair (2ip, 2ip+1).
//          Streams x from global (coalesced), stages into xt, accumulates logits.
// Finalize: threads 0..63 combine 8 c-group partials, softmax, csum.
// Phase B: thread t = channel c, consumes xt (pitch 66: conflict-free both ways).
extern "C" __global__ void __launch_bounds__(256) k_fused(const float* __restrict__ x) {
    extern __shared__ __align__(16) char dsm[];
    float* xt   = (float*)(dsm + SM_XT);     // [c*66 + i]
    ull*   usm  = (ull*)(dsm + SM_USM);      // [j*256 + c] dup-packed
    ull*   psm  = (ull*)(dsm + SM_USM);      // alias: [w*320 + ip*10 + j]
    float* cssm = (float*)(dsm + SM_CSSM);   // [j*64 + i]
    float* vbs  = (float*)(dsm + SM_VBS);
    float* csw  = (float*)(dsm + SM_CSW);

    int tile = blockIdx.x, b = blockIdx.y, t = threadIdx.x;
    int w = t >> 5, ip = t & 31;
    const float* xb = x + (size_t)b * CIN * II;
    int i0 = tile * TI;

    const float* gu = g_u + (size_t)b * J * CIN;
    #pragma unroll
    for (int k = 0; k < J; k++) usm[k * 256 + t] = dup2(gu[k * 256 + t]);
    if (t < J) vbs[t] = g_vb[b * J + t];
    __syncthreads();

    // ---- phase A + stage ----
    ull acc[J];
    #pragma unroll
    for (int j = 0; j < J; j++) acc[j] = 0ull;
    {
        const float* xc = xb + (size_t)(w * 32) * II + i0 + 2 * ip;
        #pragma unroll 4
        for (int cc = 0; cc < 16; cc++) {
            int c = w * 32 + 2 * cc;
            ull xa  = *(const ull*)(xc + (size_t)(2 * cc) * II);
            ull xb2 = *(const ull*)(xc + (size_t)(2 * cc + 1) * II);
            *(ull*)(xt + c * 66 + 2 * ip)       = xa;   // bank64 (33c+ip): CF
            *(ull*)(xt + (c + 1) * 66 + 2 * ip) = xb2;
            const ull* up = usm + c;
            #pragma unroll
            for (int j = 0; j < J; j++) {
                ulonglong2 ud = *(const ulonglong2*)(up + j * 256);  // c even: 16B ok
                ffma2(acc[j], ud.x, xa);
                ffma2(acc[j], ud.y, xb2);
            }
        }
    }
    __syncthreads();           // all usm reads done before psm overwrite
    #pragma unroll
    for (int j = 0; j < J; j++) psm[w * 320 + ip * 10 + j] = acc[j];
    __syncthreads();

    // ---- finalize: softmax per i (threads 0..63) ----
    if (t < TI) {
        int iq = t >> 1, half = t & 1;
        float lg[J];
        #pragma unroll
        for (int j = 0; j < J; j++) {
            float s = vbs[j];
            #pragma unroll
            for (int ww = 0; ww < 8; ww++)
                s += ((const float*)(psm + ww * 320 + iq * 10 + j))[half];
            lg[j] = s;
        }
        float m = lg[0];
        #pragma unroll
        for (int j = 1; j < J; j++) m = fmaxf(m, lg[j]);
        float ssum = 0.0f;
        #pragma unroll
        for (int j = 0; j < J; j++) { lg[j] = __expf(lg[j] - m); ssum += lg[j]; }
        float r = 1.0f / ssum;
        #pragma unroll
        for (int j = 0; j < J; j++) {
            float cv = lg[j] * r;
            cssm[j * TI + t] = cv;
            lg[j] = cv;
        }
        // csum: shfl-reduce over i within each of the 2 active warps
        #pragma unroll
        for (int j = 0; j < J; j++) {
            float sc = lg[j];
            #pragma unroll
            for (int o = 16; o; o >>= 1) sc += __shfl_xor_sync(0xffffffffu, sc, o);
            if (ip == 0) csw[w * 10 + j] = sc;
        }
    }
    __syncthreads();
    if (t < J) g_cpart[(b * NP + tile) * J + t] = csw[t] + csw[10 + t];

    // ---- phase B: y[j][c=t] from xt + cssm ----
    ull y0[J], y1[J];
    #pragma unroll
    for (int j = 0; j < J; j++) { y0[j] = 0ull; y1[j] = 0ull; }
    #pragma unroll 4
    for (int g = 0; g < 16; g++) {
        ull xv0 = *(const ull*)(xt + t * 66 + 4 * g);       // bank64 (t+2g): CF
        ull xv1 = *(const ull*)(xt + t * 66 + 4 * g + 2);
        const float* cp = cssm + 4 * g;
        #pragma unroll
        for (int j = 0; j < J; j++) {
            ulonglong2 cv = *(const ulonglong2*)(cp + j * TI);  // broadcast, 16B ok
            ffma2(y0[j], cv.x, xv0);
            ffma2(y1[j], cv.y, xv1);
        }
    }
    #pragma unroll
    for (int j = 0; j < J; j++)
        g_ypart[(((size_t)b * NP + tile) * J + j) * CIN + t] =
            (lo2(y0[j]) + hi2(y0[j])) + (lo2(y1[j]) + hi2(y1[j]));
}

// ---------------- launch ----------------
extern "C" void kernel_launch(void* const* d_in, const int* in_sizes, int n_in,
                              void* d_out, int out_size) {
    const float* x  = (const float*)d_in[0];   // [64,256,32,32]
    const float* W  = (const float*)d_in[1];   // [320,256]
    const float* Wb = (const float*)d_in[2];   // [320]
    float* out = (float*)d_out;                // [64,10,32]

    cudaFuncSetAttribute((const void*)k_fused,
                         cudaFuncAttributeMaxDynamicSharedMemorySize, SM_TOT);

    k_xsum <<<BS * CIN / 8, 256>>>(x);
    k_sv   <<<dim3(J, BS), 256>>>(W, Wb, out, 0);     // iter1: v1, u1, vb1
    k_fused<<<dim3(NP, BS), 256, SM_TOT>>>(x);        // iter2 pass (x read once)
    k_sv   <<<dim3(J, BS), 256>>>(W, Wb, out, 1);     // iter2: v2, u+=, vb+=
    k_fused<<<dim3(NP, BS), 256, SM_TOT>>>(x);        // iter3 pass
    k_sv   <<<dim3(J, BS), 256>>>(W, Wb, out, 2);     // iter3: v3 -> out
}